// round 14
// baseline (speedup 1.0000x reference)
#include <cuda_runtime.h>
#include <cstdint>

#define NTOK 4096
#define DDIM 1024
#define HDIM 2048
#define NEXP 8

// ---------------- scratch (static __device__, allocation-free) ----------------
__device__ float g_xr [(size_t)NTOK * DDIM];                // tf32-rounded x
__device__ float g_w1r[(size_t)NEXP * DDIM * HDIM];         // tf32-rounded w1
__device__ float g_w2r[(size_t)NEXP * HDIM * DDIM];         // tf32-rounded w2
__device__ float g_hbuf[(size_t)NEXP * NTOK * HDIM];        // gelu(h) per slot (tf32-rounded)
__device__ float g_ybuf[(size_t)NEXP * NTOK * DDIM];        // expert outputs
__device__ int   g_counts[NEXP];
__device__ int   g_tok [NEXP * NTOK];                       // expert -> token list
__device__ int   g_expi[NTOK * 2];
__device__ int   g_slot[NTOK * 2];
__device__ float g_gate[NTOK * 2];
// persistent-scheduler state
__device__ int   g_pairs[NEXP * (NTOK / 128)];              // (e<<8)|tm live tiles
__device__ int   g_npairs;
__device__ int   g_work1;
__device__ int   g_work2;

// ---------------- helpers ----------------
__device__ __forceinline__ uint32_t tf32_bits(float v) {    // round-to-nearest tf32
    uint32_t r;
    asm("cvt.rna.tf32.f32 %0, %1;" : "=r"(r) : "f"(v));
    return r;
}
__device__ __forceinline__ float tf32_round(float v) { return __uint_as_float(tf32_bits(v)); }

__device__ __forceinline__ void cpasync16(void* s, const void* g) {
    uint32_t sa = (uint32_t)__cvta_generic_to_shared(s);
    asm volatile("cp.async.cg.shared.global [%0], [%1], 16;" :: "r"(sa), "l"(g));
}
__device__ __forceinline__ void cp_commit() { asm volatile("cp.async.commit_group;"); }
__device__ __forceinline__ void cp_wait2()  { asm volatile("cp.async.wait_group 2;"); }
__device__ __forceinline__ void cp_wait0()  { asm volatile("cp.async.wait_group 0;"); }

__device__ __forceinline__ void mma_tf32(float* c, const uint32_t* a, const uint32_t* b) {
    asm volatile(
        "mma.sync.aligned.m16n8k8.row.col.f32.tf32.tf32.f32 "
        "{%0,%1,%2,%3}, {%4,%5,%6,%7}, {%8,%9}, {%0,%1,%2,%3};"
        : "+f"(c[0]), "+f"(c[1]), "+f"(c[2]), "+f"(c[3])
        : "r"(a[0]), "r"(a[1]), "r"(a[2]), "r"(a[3]), "r"(b[0]), "r"(b[1]));
}

// JAX default gelu: approximate=True (tanh form)
__device__ __forceinline__ float gelu_tanh(float v) {
    float t = tanhf(0.7978845608028654f * (v + 0.044715f * v * v * v));
    return 0.5f * v * (1.0f + t);
}

// ---------------- stage 0: zero counts ----------------
__global__ void zero_counts_kernel() {
    if (threadIdx.x < NEXP) g_counts[threadIdx.x] = 0;
}

// ---------------- stage 0b: tf32 pre-round ----------------
__global__ void round_tf32_kernel(const float4* __restrict__ in, float4* __restrict__ outp, int n4) {
    int i = blockIdx.x * blockDim.x + threadIdx.x;
    if (i < n4) {
        float4 v = in[i];
        v.x = tf32_round(v.x); v.y = tf32_round(v.y);
        v.z = tf32_round(v.z); v.w = tf32_round(v.w);
        outp[i] = v;
    }
}

// ---------------- stage 1: gating (top-2 softmax + expert lists) ----------------
__global__ void gate_kernel(const float* __restrict__ x, const float* __restrict__ wg) {
    const int n = blockIdx.x;
    const int tid = threadIdx.x;                 // 128 threads
    const float* xr = x + (size_t)n * DDIM;

    float acc[NEXP];
#pragma unroll
    for (int e = 0; e < NEXP; e++) acc[e] = 0.0f;
    for (int d = tid; d < DDIM; d += 128) {
        float xv = xr[d];
        const float* w = wg + d * NEXP;
#pragma unroll
        for (int e = 0; e < NEXP; e++) acc[e] += xv * w[e];
    }
#pragma unroll
    for (int e = 0; e < NEXP; e++) {
#pragma unroll
        for (int o = 16; o > 0; o >>= 1) acc[e] += __shfl_xor_sync(0xffffffffu, acc[e], o);
    }
    __shared__ float sred[4][NEXP];
    const int wid = tid >> 5, lane = tid & 31;
    if (lane == 0) {
#pragma unroll
        for (int e = 0; e < NEXP; e++) sred[wid][e] = acc[e];
    }
    __syncthreads();
    if (tid == 0) {
        float lg[NEXP];
#pragma unroll
        for (int e = 0; e < NEXP; e++)
            lg[e] = sred[0][e] + sred[1][e] + sred[2][e] + sred[3][e];
        int i0 = 0;
#pragma unroll
        for (int e = 1; e < NEXP; e++) if (lg[e] > lg[i0]) i0 = e;
        int i1 = (i0 == 0) ? 1 : 0;
#pragma unroll
        for (int e = 0; e < NEXP; e++) if (e != i0 && lg[e] > lg[i1]) i1 = e;
        float e1 = __expf(lg[i1] - lg[i0]);
        float inv = 1.0f / (1.0f + e1);

        int s0 = atomicAdd(&g_counts[i0], 1);
        int s1 = atomicAdd(&g_counts[i1], 1);
        g_tok[i0 * NTOK + s0] = n;
        g_tok[i1 * NTOK + s1] = n;
        g_expi[n * 2 + 0] = i0;  g_slot[n * 2 + 0] = s0;  g_gate[n * 2 + 0] = inv;
        g_expi[n * 2 + 1] = i1;  g_slot[n * 2 + 1] = s1;  g_gate[n * 2 + 1] = e1 * inv;
    }
}

// ---------------- stage 1b: enumerate live tiles, reset work counters ----------------
__global__ void build_tiles_kernel() {
    if (threadIdx.x == 0) {
        int n = 0;
        for (int e = 0; e < NEXP; e++) {
            const int nt = (g_counts[e] + 127) >> 7;
            for (int tm = 0; tm < nt; tm++) g_pairs[n++] = (e << 8) | tm;
        }
        g_npairs = n;
        g_work1 = 0;
        g_work2 = 0;
    }
}

// ---------------- stages 2/3: persistent grouped GEMM, tf32 mma.sync ----------------
// Tile 128(tokens) x 128(cols), BK=16, 4-stage cp.async, 256 thr, 2 CTAs/SM.
// PERSISTENT: CTAs pull (e,tm,tn) tiles from a global atomic counter over the
// exact live-tile list — removes wave quantization + dead-block skew (the
// chip-level residual left after four neutral inner-loop rounds).

#define A_STRIDE 20          // floats per A smem row (rows hit distinct banks)
#define B_STRIDE 136         // floats per B smem row (136%32=8 -> conflict-free frags)
#define A_STAGE  (128 * A_STRIDE)            // 2560 floats
#define B_STAGE  (16 * B_STRIDE)             // 2176 floats
#define SMEM_FLOATS (4 * (A_STAGE + B_STAGE))
#define SMEM_BYTES  (SMEM_FLOATS * 4)        // 75,776 B -> 2 CTAs/SM

template <int PHASE>
__global__ void __launch_bounds__(256, 2) ffn_gemm_kernel(
    const float* __restrict__ x, const float* __restrict__ w_all,
    const float* __restrict__ bias_all) {
    constexpr int KD   = (PHASE == 1) ? DDIM : HDIM;
    constexpr int NOUT = (PHASE == 1) ? HDIM : DDIM;
    constexpr int KT   = KD / 16;
    constexpr int TN   = NOUT / 128;

    extern __shared__ float smem[];
    float* const Abase = smem;                       // 4 stages x A_STAGE
    float* const Bbase = smem + 4 * A_STAGE;         // 4 stages x B_STAGE
    __shared__ int s_t;

    const int tid  = threadIdx.x;
    const int lane = tid & 31, wid = tid >> 5;
    const int wm = wid >> 2, wn = wid & 3;           // 2 x 4 warp grid, 64x32 per warp
    const int grp = lane >> 2, tig = lane & 3;

    int* workp = (PHASE == 1) ? &g_work1 : &g_work2;
    const int ntiles_mul = TN;

    // tile-invariant smem offsets
    const int ar_ = tid >> 2, ac_ = (tid & 3) * 4;   // A chunk (1st of 2)
    const int aoff0 = ar_ * A_STRIDE + ac_;
    const int ar2_ = (256 + tid) >> 2, ac2_ = ((256 + tid) & 3) * 4;
    const int aoff1 = ar2_ * A_STRIDE + ac2_;
    const int br_ = tid >> 5, bc_ = (tid & 31) * 4;  // B chunk (1st of 2)
    const int boff0 = br_ * B_STRIDE + bc_;
    const int br2_ = (256 + tid) >> 5, bc2_ = ((256 + tid) & 31) * 4;
    const int boff1 = br2_ * B_STRIDE + bc2_;

    for (;;) {
        if (tid == 0) s_t = atomicAdd(workp, 1);
        __syncthreads();                             // broadcast t; also guards smem reuse
        const int t = s_t;
        if (t >= g_npairs * ntiles_mul) break;

        const int pair = g_pairs[t / TN];
        const int tn   = t % TN;                     // tn fastest: consecutive tiles share A
        const int e    = pair >> 8;
        const int tm   = pair & 255;
        const int cnt  = g_counts[e];
        const int rows = min(128, cnt - tm * 128);

        // ---- per-tile load pointers ----
        const float* wsrc = w_all + (size_t)e * ((size_t)KD * NOUT);
        const float* ag[2];
        if (PHASE == 1) {
            ag[0] = x + (size_t)g_tok[e * NTOK + tm * 128 + ar_]  * DDIM + ac_;
            ag[1] = x + (size_t)g_tok[e * NTOK + tm * 128 + ar2_] * DDIM + ac2_;
        } else {
            ag[0] = g_hbuf + ((size_t)e * NTOK + tm * 128 + ar_)  * HDIM + ac_;
            ag[1] = g_hbuf + ((size_t)e * NTOK + tm * 128 + ar2_) * HDIM + ac2_;
        }
        const float* bg[2] = {
            wsrc + (size_t)br_  * NOUT + (size_t)tn * 128 + bc_,
            wsrc + (size_t)br2_ * NOUT + (size_t)tn * 128 + bc2_,
        };

        auto issue = [&](int it, int stage) {
            float* As = Abase + stage * A_STAGE;
            float* Bs = Bbase + stage * B_STAGE;
            cpasync16(As + aoff0, ag[0] + it * 16);
            cpasync16(As + aoff1, ag[1] + it * 16);
            cpasync16(Bs + boff0, bg[0] + (size_t)it * 16 * NOUT);
            cpasync16(Bs + boff1, bg[1] + (size_t)it * 16 * NOUT);
        };

        float acc[4][4][4];
#pragma unroll
        for (int mi = 0; mi < 4; mi++)
#pragma unroll
            for (int ni = 0; ni < 4; ni++)
#pragma unroll
                for (int q = 0; q < 4; q++) acc[mi][ni][q] = 0.0f;

        // ---- prologue: 3 stages in flight ----
        issue(0, 0); cp_commit();
        issue(1, 1); cp_commit();
        issue(2, 2); cp_commit();

        for (int it = 0; it < KT; it++) {
            const int stage = it & 3;
            cp_wait2();                              // stage `it` landed
            __syncthreads();                         // everyone done reading stage (it-1)&3
            if (it + 3 < KT) issue(it + 3, (it + 3) & 3);
            cp_commit();                             // empty commit at tail keeps count math

            const float* As = Abase + stage * A_STAGE;
            const float* Bs = Bbase + stage * B_STAGE;
#pragma unroll
            for (int kk = 0; kk < 2; kk++) {
                uint32_t af[4][4], bf[4][2];
                const int c0 = kk * 8 + tig;
#pragma unroll
                for (int mi = 0; mi < 4; mi++) {
                    const int r = wm * 64 + mi * 16 + grp;
                    af[mi][0] = __float_as_uint(As[r * A_STRIDE + c0]);
                    af[mi][1] = __float_as_uint(As[(r + 8) * A_STRIDE + c0]);
                    af[mi][2] = __float_as_uint(As[r * A_STRIDE + c0 + 4]);
                    af[mi][3] = __float_as_uint(As[(r + 8) * A_STRIDE + c0 + 4]);
                }
#pragma unroll
                for (int ni = 0; ni < 4; ni++) {
                    const int nc = wn * 32 + ni * 8 + grp;
                    bf[ni][0] = __float_as_uint(Bs[(kk * 8 + tig) * B_STRIDE + nc]);
                    bf[ni][1] = __float_as_uint(Bs[(kk * 8 + 4 + tig) * B_STRIDE + nc]);
                }
#pragma unroll
                for (int mi = 0; mi < 4; mi++)
#pragma unroll
                    for (int ni = 0; ni < 4; ni++)
                        mma_tf32(acc[mi][ni], af[mi], bf[ni]);
            }
        }
        cp_wait0();                                  // drain tail empty-groups before next tile

        // ---- epilogue (registers only; loop-top barrier guards smem) ----
        const float* bias = bias_all + e * NOUT;
        float* obuf = (PHASE == 1) ? g_hbuf : g_ybuf;
        const size_t rowbase = (size_t)e * NTOK + (size_t)tm * 128;
#pragma unroll
        for (int mi = 0; mi < 4; mi++) {
            const int lr0 = wm * 64 + mi * 16 + grp;
            const int lr1 = lr0 + 8;
#pragma unroll
            for (int ni = 0; ni < 4; ni++) {
                const int col = tn * 128 + wn * 32 + ni * 8 + tig * 2;
                const float bv0 = bias[col], bv1 = bias[col + 1];
                float v00 = acc[mi][ni][0] + bv0, v01 = acc[mi][ni][1] + bv1;
                float v10 = acc[mi][ni][2] + bv0, v11 = acc[mi][ni][3] + bv1;
                if (PHASE == 1) {
                    v00 = tf32_round(gelu_tanh(v00)); v01 = tf32_round(gelu_tanh(v01));
                    v10 = tf32_round(gelu_tanh(v10)); v11 = tf32_round(gelu_tanh(v11));
                }
                if (lr0 < rows)
                    *(float2*)(obuf + (rowbase + lr0) * NOUT + col) = make_float2(v00, v01);
                if (lr1 < rows)
                    *(float2*)(obuf + (rowbase + lr1) * NOUT + col) = make_float2(v10, v11);
            }
        }
    }
}

// ---------------- stage 4: combine top-2 ----------------
__global__ void combine_kernel(float* __restrict__ out) {
    const int n = blockIdx.x;
    const int tid = threadIdx.x;                 // 256 threads, D/4 float4
    const int e0 = g_expi[n * 2], e1 = g_expi[n * 2 + 1];
    const int s0 = g_slot[n * 2], s1 = g_slot[n * 2 + 1];
    const float gg0 = g_gate[n * 2], gg1 = g_gate[n * 2 + 1];
    const float4* r0 = (const float4*)(g_ybuf + ((size_t)e0 * NTOK + s0) * DDIM);
    const float4* r1 = (const float4*)(g_ybuf + ((size_t)e1 * NTOK + s1) * DDIM);
    float4* o = (float4*)(out + (size_t)n * DDIM);
    float4 a = r0[tid], b = r1[tid];
    o[tid] = make_float4(gg0 * a.x + gg1 * b.x, gg0 * a.y + gg1 * b.y,
                         gg0 * a.z + gg1 * b.z, gg0 * a.w + gg1 * b.w);
}

// ---------------- launch ----------------
extern "C" void kernel_launch(void* const* d_in, const int* in_sizes, int n_in,
                              void* d_out, int out_size) {
    const float* x  = (const float*)d_in[0];   // [N, D]
    const float* wg = (const float*)d_in[1];   // [D, E]
    const float* w1 = (const float*)d_in[2];   // [E, D, H]
    const float* b1 = (const float*)d_in[3];   // [E, H]
    const float* w2 = (const float*)d_in[4];   // [E, H, D]
    const float* b2 = (const float*)d_in[5];   // [E, D]
    float* out = (float*)d_out;

    float* xr;  cudaGetSymbolAddress((void**)&xr,  g_xr);
    float* w1r; cudaGetSymbolAddress((void**)&w1r, g_w1r);
    float* w2r; cudaGetSymbolAddress((void**)&w2r, g_w2r);

    cudaFuncSetAttribute(ffn_gemm_kernel<1>, cudaFuncAttributeMaxDynamicSharedMemorySize, SMEM_BYTES);
    cudaFuncSetAttribute(ffn_gemm_kernel<2>, cudaFuncAttributeMaxDynamicSharedMemorySize, SMEM_BYTES);

    zero_counts_kernel<<<1, NEXP>>>();
    gate_kernel<<<NTOK, 128>>>(x, wg);
    build_tiles_kernel<<<1, 32>>>();

    {   // pre-round: removes every CVT from both GEMM mainloops
        int n4 = NTOK * DDIM / 4;
        round_tf32_kernel<<<(n4 + 255) / 256, 256>>>((const float4*)x, (float4*)xr, n4);
        int m4 = NEXP * DDIM * HDIM / 4;
        round_tf32_kernel<<<(m4 + 255) / 256, 256>>>((const float4*)w1, (float4*)w1r, m4);
        round_tf32_kernel<<<(m4 + 255) / 256, 256>>>((const float4*)w2, (float4*)w2r, m4);
    }

    // persistent: 2 CTAs per SM (152 SMs on GB300) pull tiles via atomic counter
    ffn_gemm_kernel<1><<<304, 256, SMEM_BYTES>>>(xr, w1r, b1);
    ffn_gemm_kernel<2><<<304, 256, SMEM_BYTES>>>(xr, w2r, b2);

    combine_kernel<<<NTOK, 256>>>(out);
}

// round 15
// speedup vs baseline: 1.9673x; 1.9673x over previous
#include <cuda_runtime.h>
#include <cuda_fp16.h>
#include <cstdint>

#define NTOK 4096
#define DDIM 1024
#define HDIM 2048
#define NEXP 8

// ---------------- scratch (static __device__, allocation-free) ----------------
__device__ __half g_xh [(size_t)NTOK * DDIM];               // fp16 x
__device__ __half g_w1h[(size_t)NEXP * DDIM * HDIM];        // fp16 w1
__device__ __half g_w2h[(size_t)NEXP * HDIM * DDIM];        // fp16 w2
__device__ __half g_hh [(size_t)NEXP * NTOK * HDIM];        // fp16 gelu(h) per slot
__device__ float  g_ybuf[(size_t)NEXP * NTOK * DDIM];       // expert outputs (fp32)
__device__ int    g_counts[NEXP];
__device__ int    g_tok [NEXP * NTOK];                      // expert -> token list
__device__ int    g_expi[NTOK * 2];
__device__ int    g_slot[NTOK * 2];
__device__ float  g_gate[NTOK * 2];

// ---------------- helpers ----------------
__device__ __forceinline__ void cpasync16(void* s, const void* g) {
    uint32_t sa = (uint32_t)__cvta_generic_to_shared(s);
    asm volatile("cp.async.cg.shared.global [%0], [%1], 16;" :: "r"(sa), "l"(g));
}
__device__ __forceinline__ void cp_commit() { asm volatile("cp.async.commit_group;"); }
__device__ __forceinline__ void cp_wait2()  { asm volatile("cp.async.wait_group 2;"); }

// fp16 MMA: m16n8k16, fp32 accum — 2x FLOPs/instr vs m16n8k8.tf32
__device__ __forceinline__ void mma_f16(float* c, const uint32_t* a, const uint32_t* b) {
    asm volatile(
        "mma.sync.aligned.m16n8k16.row.col.f32.f16.f16.f32 "
        "{%0,%1,%2,%3}, {%4,%5,%6,%7}, {%8,%9}, {%0,%1,%2,%3};"
        : "+f"(c[0]), "+f"(c[1]), "+f"(c[2]), "+f"(c[3])
        : "r"(a[0]), "r"(a[1]), "r"(a[2]), "r"(a[3]), "r"(b[0]), "r"(b[1]));
}
__device__ __forceinline__ void ldsm_x4(uint32_t* r, uint32_t saddr) {
    asm volatile("ldmatrix.sync.aligned.m8n8.x4.shared.b16 {%0,%1,%2,%3}, [%4];"
                 : "=r"(r[0]), "=r"(r[1]), "=r"(r[2]), "=r"(r[3]) : "r"(saddr));
}
__device__ __forceinline__ void ldsm_x4_t(uint32_t* r, uint32_t saddr) {
    asm volatile("ldmatrix.sync.aligned.m8n8.x4.trans.shared.b16 {%0,%1,%2,%3}, [%4];"
                 : "=r"(r[0]), "=r"(r[1]), "=r"(r[2]), "=r"(r[3]) : "r"(saddr));
}

// JAX default gelu: approximate=True (tanh form)
__device__ __forceinline__ float gelu_tanh(float v) {
    float t = tanhf(0.7978845608028654f * (v + 0.044715f * v * v * v));
    return 0.5f * v * (1.0f + t);
}

// ---------------- stage 0: zero counts ----------------
__global__ void zero_counts_kernel() {
    if (threadIdx.x < NEXP) g_counts[threadIdx.x] = 0;
}

// ---------------- stage 0b: fp32 -> fp16 convert ----------------
__global__ void to_half_kernel(const float4* __restrict__ in, __half2* __restrict__ outp, int n4) {
    int i = blockIdx.x * blockDim.x + threadIdx.x;
    if (i < n4) {
        float4 v = in[i];
        outp[2 * i + 0] = __floats2half2_rn(v.x, v.y);
        outp[2 * i + 1] = __floats2half2_rn(v.z, v.w);
    }
}

// ---------------- stage 1: gating (top-2 softmax + expert lists) ----------------
__global__ void gate_kernel(const float* __restrict__ x, const float* __restrict__ wg) {
    const int n = blockIdx.x;
    const int tid = threadIdx.x;                 // 128 threads
    const float* xr = x + (size_t)n * DDIM;

    float acc[NEXP];
#pragma unroll
    for (int e = 0; e < NEXP; e++) acc[e] = 0.0f;
    for (int d = tid; d < DDIM; d += 128) {
        float xv = xr[d];
        const float* w = wg + d * NEXP;
#pragma unroll
        for (int e = 0; e < NEXP; e++) acc[e] += xv * w[e];
    }
#pragma unroll
    for (int e = 0; e < NEXP; e++) {
#pragma unroll
        for (int o = 16; o > 0; o >>= 1) acc[e] += __shfl_xor_sync(0xffffffffu, acc[e], o);
    }
    __shared__ float sred[4][NEXP];
    const int wid = tid >> 5, lane = tid & 31;
    if (lane == 0) {
#pragma unroll
        for (int e = 0; e < NEXP; e++) sred[wid][e] = acc[e];
    }
    __syncthreads();
    if (tid == 0) {
        float lg[NEXP];
#pragma unroll
        for (int e = 0; e < NEXP; e++)
            lg[e] = sred[0][e] + sred[1][e] + sred[2][e] + sred[3][e];
        int i0 = 0;
#pragma unroll
        for (int e = 1; e < NEXP; e++) if (lg[e] > lg[i0]) i0 = e;
        int i1 = (i0 == 0) ? 1 : 0;
#pragma unroll
        for (int e = 0; e < NEXP; e++) if (e != i0 && lg[e] > lg[i1]) i1 = e;
        float e1 = __expf(lg[i1] - lg[i0]);
        float inv = 1.0f / (1.0f + e1);

        int s0 = atomicAdd(&g_counts[i0], 1);
        int s1 = atomicAdd(&g_counts[i1], 1);
        g_tok[i0 * NTOK + s0] = n;
        g_tok[i1 * NTOK + s1] = n;
        g_expi[n * 2 + 0] = i0;  g_slot[n * 2 + 0] = s0;  g_gate[n * 2 + 0] = inv;
        g_expi[n * 2 + 1] = i1;  g_slot[n * 2 + 1] = s1;  g_gate[n * 2 + 1] = e1 * inv;
    }
}

// ---------------- stages 2/3: grouped GEMM, fp16 mma.sync m16n8k16 ----------------
// Tile 128(tokens) x 128(cols), BK=32, 4-stage cp.async, 256 thr, 2 CTAs/SM.
// fp16 has the SAME 10-bit mantissa as tf32 (exponent range is the only diff,
// and all values here are ~1e-3..10): precision matches the measured 4.2e-4.
// m16n8k16 does 2x FLOPs/instruction vs m16n8k8.tf32 -> HALF the MMA
// instructions, attacking the per-instruction MMA-rate wall that five
// structural rounds could not move. Fragments via ldmatrix (A) and
// ldmatrix.trans (B, consumed straight from [k][n] layout).

#define A_STRIDE 40          // halfs per A smem row (32 k + 8 pad; rows bank-disjoint)
#define B_STRIDE 136         // halfs per B smem row (128 n + 8 pad; k-rows bank-disjoint)
#define A_STAGE  (128 * A_STRIDE)            // 5120 halfs
#define B_STAGE  (32 * B_STRIDE)             // 4352 halfs
#define SMEM_HALFS (4 * (A_STAGE + B_STAGE))
#define SMEM_BYTES (SMEM_HALFS * 2)          // 75,776 B -> 2 CTAs/SM

template <int PHASE>
__global__ void __launch_bounds__(256, 2) ffn_gemm_kernel(
    const __half* __restrict__ x, const __half* __restrict__ w_all,
    const float* __restrict__ bias_all) {
    constexpr int KD   = (PHASE == 1) ? DDIM : HDIM;
    constexpr int NOUT = (PHASE == 1) ? HDIM : DDIM;
    constexpr int KT   = KD / 32;

    const int e  = blockIdx.z;
    const int tm = blockIdx.y;
    const int tn = blockIdx.x;
    const int cnt = g_counts[e];
    if (tm * 128 >= cnt) return;
    const int rows = min(128, cnt - tm * 128);

    extern __shared__ __half smem[];
    __half* const Abase = smem;                      // 4 stages x A_STAGE
    __half* const Bbase = smem + 4 * A_STAGE;        // 4 stages x B_STAGE
    const uint32_t sbase = (uint32_t)__cvta_generic_to_shared(smem);

    const int tid  = threadIdx.x;
    const int lane = tid & 31, wid = tid >> 5;
    const int wm = wid >> 2, wn = wid & 3;           // 2 x 4 warp grid, 64x32 per warp
    const int grp = lane >> 2, tig = lane & 3;

    // ---- per-thread cp.async assignments ----
    // A: 128 rows x 32 halfs(64B) = 512 x 16B chunks; 2 per thread
    const __half* ag[2];
    int aoff[2];
    const __half* wsrc = w_all + (size_t)e * ((size_t)KD * NOUT);
#pragma unroll
    for (int j = 0; j < 2; j++) {
        const int linear = j * 256 + tid;
        const int ar = linear >> 2;                  // row 0..127
        const int ac = (linear & 3) * 8;             // half offset 0/8/16/24
        if (PHASE == 1) {
            const int tk = g_tok[e * NTOK + tm * 128 + ar];
            ag[j] = x + (size_t)tk * DDIM + ac;
        } else {
            ag[j] = g_hh + ((size_t)e * NTOK + tm * 128 + ar) * HDIM + ac;
        }
        aoff[j] = ar * A_STRIDE + ac;
    }
    // B: 32 k-rows x 128 n-halfs(256B) = 512 x 16B chunks; 2 per thread
    const __half* bg[2];
    int boff[2];
#pragma unroll
    for (int j = 0; j < 2; j++) {
        const int linear = j * 256 + tid;
        const int br = linear >> 4;                  // k-row 0..31
        const int bc = (linear & 15) * 8;            // n-half offset 0..120
        bg[j]   = wsrc + (size_t)br * NOUT + (size_t)tn * 128 + bc;
        boff[j] = br * B_STRIDE + bc;
    }

    auto issue = [&](int it, int stage) {
        __half* As = Abase + stage * A_STAGE;
        __half* Bs = Bbase + stage * B_STAGE;
#pragma unroll
        for (int j = 0; j < 2; j++) cpasync16(As + aoff[j], ag[j] + it * 32);
#pragma unroll
        for (int j = 0; j < 2; j++) cpasync16(Bs + boff[j], bg[j] + (size_t)it * 32 * NOUT);
    };

    // ---- ldmatrix lane address components (in halfs; x2 for bytes) ----
    const int l15 = lane & 15, lhi = lane >> 4;
    // A x4 (mi,ks): rows r0+l15 @ kbase + lhi*8
    const int aLane = (wm * 64 + l15) * A_STRIDE + lhi * 8;
    // B x4.trans (p,ks): k-rows ks*16+l15 @ ncol wn*32 + p*16 + lhi*8
    const int bLane = l15 * B_STRIDE + wn * 32 + lhi * 8;

    float acc[4][4][4];
#pragma unroll
    for (int mi = 0; mi < 4; mi++)
#pragma unroll
        for (int ni = 0; ni < 4; ni++)
#pragma unroll
            for (int q = 0; q < 4; q++) acc[mi][ni][q] = 0.0f;

    // ---- prologue: 3 stages in flight ----
    issue(0, 0); cp_commit();
    issue(1, 1); cp_commit();
    issue(2, 2); cp_commit();

    for (int it = 0; it < KT; it++) {
        const int stage = it & 3;
        cp_wait2();                                  // stage `it` landed
        __syncthreads();                             // everyone done reading stage (it-1)&3
        if (it + 3 < KT) issue(it + 3, (it + 3) & 3);
        cp_commit();                                 // empty commit at tail keeps count math

        const uint32_t aSt = sbase + (uint32_t)((stage * A_STAGE + aLane) * 2);
        const uint32_t bSt = sbase + (uint32_t)((4 * A_STAGE + stage * B_STAGE + bLane) * 2);
#pragma unroll
        for (int ks = 0; ks < 2; ks++) {             // two k16 steps per BK=32
            uint32_t af[4][4], bf[4][2];
#pragma unroll
            for (int mi = 0; mi < 4; mi++)
                ldsm_x4(af[mi], aSt + (uint32_t)((mi * 16 * A_STRIDE + ks * 16) * 2));
#pragma unroll
            for (int p = 0; p < 2; p++) {
                uint32_t t[4];
                ldsm_x4_t(t, bSt + (uint32_t)((ks * 16 * B_STRIDE + p * 16) * 2));
                bf[2 * p][0] = t[0]; bf[2 * p][1] = t[1];
                bf[2 * p + 1][0] = t[2]; bf[2 * p + 1][1] = t[3];
            }
#pragma unroll
            for (int mi = 0; mi < 4; mi++)
#pragma unroll
                for (int ni = 0; ni < 4; ni++)
                    mma_f16(acc[mi][ni], af[mi], bf[ni]);
        }
        // no trailing sync: next iteration's leading sync protects stage reuse
    }

    // ---- epilogue ----
    const float* bias = bias_all + e * NOUT;
    const size_t rowbase = (size_t)e * NTOK + (size_t)tm * 128;
#pragma unroll
    for (int mi = 0; mi < 4; mi++) {
        const int lr0 = wm * 64 + mi * 16 + grp;
        const int lr1 = lr0 + 8;
#pragma unroll
        for (int ni = 0; ni < 4; ni++) {
            const int col = tn * 128 + wn * 32 + ni * 8 + tig * 2;
            const float bv0 = bias[col], bv1 = bias[col + 1];
            float v00 = acc[mi][ni][0] + bv0, v01 = acc[mi][ni][1] + bv1;
            float v10 = acc[mi][ni][2] + bv0, v11 = acc[mi][ni][3] + bv1;
            if (PHASE == 1) {
                // gelu in fp32, store h as fp16 (feeds GEMM2's fp16 A operand)
                __half2 h0 = __floats2half2_rn(gelu_tanh(v00), gelu_tanh(v01));
                __half2 h1 = __floats2half2_rn(gelu_tanh(v10), gelu_tanh(v11));
                if (lr0 < rows)
                    *(__half2*)(g_hh + (rowbase + lr0) * HDIM + col) = h0;
                if (lr1 < rows)
                    *(__half2*)(g_hh + (rowbase + lr1) * HDIM + col) = h1;
            } else {
                if (lr0 < rows)
                    *(float2*)(g_ybuf + (rowbase + lr0) * DDIM + col) = make_float2(v00, v01);
                if (lr1 < rows)
                    *(float2*)(g_ybuf + (rowbase + lr1) * DDIM + col) = make_float2(v10, v11);
            }
        }
    }
}

// ---------------- stage 4: combine top-2 ----------------
__global__ void combine_kernel(float* __restrict__ out) {
    const int n = blockIdx.x;
    const int tid = threadIdx.x;                 // 256 threads, D/4 float4
    const int e0 = g_expi[n * 2], e1 = g_expi[n * 2 + 1];
    const int s0 = g_slot[n * 2], s1 = g_slot[n * 2 + 1];
    const float gg0 = g_gate[n * 2], gg1 = g_gate[n * 2 + 1];
    const float4* r0 = (const float4*)(g_ybuf + ((size_t)e0 * NTOK + s0) * DDIM);
    const float4* r1 = (const float4*)(g_ybuf + ((size_t)e1 * NTOK + s1) * DDIM);
    float4* o = (float4*)(out + (size_t)n * DDIM);
    float4 a = r0[tid], b = r1[tid];
    o[tid] = make_float4(gg0 * a.x + gg1 * b.x, gg0 * a.y + gg1 * b.y,
                         gg0 * a.z + gg1 * b.z, gg0 * a.w + gg1 * b.w);
}

// ---------------- launch ----------------
extern "C" void kernel_launch(void* const* d_in, const int* in_sizes, int n_in,
                              void* d_out, int out_size) {
    const float* x  = (const float*)d_in[0];   // [N, D]
    const float* wg = (const float*)d_in[1];   // [D, E]
    const float* w1 = (const float*)d_in[2];   // [E, D, H]
    const float* b1 = (const float*)d_in[3];   // [E, H]
    const float* w2 = (const float*)d_in[4];   // [E, H, D]
    const float* b2 = (const float*)d_in[5];   // [E, D]
    float* out = (float*)d_out;

    __half* xh;  cudaGetSymbolAddress((void**)&xh,  g_xh);
    __half* w1h; cudaGetSymbolAddress((void**)&w1h, g_w1h);
    __half* w2h; cudaGetSymbolAddress((void**)&w2h, g_w2h);

    cudaFuncSetAttribute(ffn_gemm_kernel<1>, cudaFuncAttributeMaxDynamicSharedMemorySize, SMEM_BYTES);
    cudaFuncSetAttribute(ffn_gemm_kernel<2>, cudaFuncAttributeMaxDynamicSharedMemorySize, SMEM_BYTES);

    zero_counts_kernel<<<1, NEXP>>>();
    gate_kernel<<<NTOK, 128>>>(x, wg);

    {   // fp32 -> fp16 conversion (half the write bytes of the old tf32 prep)
        int n4 = NTOK * DDIM / 4;
        to_half_kernel<<<(n4 + 255) / 256, 256>>>((const float4*)x, (__half2*)xh, n4);
        int m4 = NEXP * DDIM * HDIM / 4;
        to_half_kernel<<<(m4 + 255) / 256, 256>>>((const float4*)w1, (__half2*)w1h, m4);
        to_half_kernel<<<(m4 + 255) / 256, 256>>>((const float4*)w2, (__half2*)w2h, m4);
    }

    ffn_gemm_kernel<1><<<dim3(HDIM / 128, NTOK / 128, NEXP), 256, SMEM_BYTES>>>(xh, w1h, b1);
    ffn_gemm_kernel<2><<<dim3(DDIM / 128, NTOK / 128, NEXP), 256, SMEM_BYTES>>>(xh, w2h, b2);

    combine_kernel<<<NTOK, 256>>>(out);
}

// round 16
// speedup vs baseline: 1.9820x; 1.0075x over previous
#include <cuda_runtime.h>
#include <cuda_fp16.h>
#include <cstdint>

#define NTOK 4096
#define DDIM 1024
#define HDIM 2048
#define NEXP 8

// ---------------- scratch (static __device__, allocation-free) ----------------
__device__ __half g_xh [(size_t)NTOK * DDIM];               // fp16 x
__device__ __half g_w1h[(size_t)NEXP * DDIM * HDIM];        // fp16 w1
__device__ __half g_w2h[(size_t)NEXP * HDIM * DDIM];        // fp16 w2
__device__ __half g_hh [(size_t)NEXP * NTOK * HDIM];        // fp16 gelu(h) per slot
__device__ int    g_counts[NEXP];
__device__ int    g_tok  [NEXP * NTOK];                     // expert -> token list
__device__ float  g_gslot[NEXP * NTOK];                     // gate weight per slot

// ---------------- helpers ----------------
__device__ __forceinline__ void cpasync16(void* s, const void* g) {
    uint32_t sa = (uint32_t)__cvta_generic_to_shared(s);
    asm volatile("cp.async.cg.shared.global [%0], [%1], 16;" :: "r"(sa), "l"(g));
}
__device__ __forceinline__ void cp_commit() { asm volatile("cp.async.commit_group;"); }
__device__ __forceinline__ void cp_wait2()  { asm volatile("cp.async.wait_group 2;"); }

// fp16 MMA: m16n8k16, fp32 accum
__device__ __forceinline__ void mma_f16(float* c, const uint32_t* a, const uint32_t* b) {
    asm volatile(
        "mma.sync.aligned.m16n8k16.row.col.f32.f16.f16.f32 "
        "{%0,%1,%2,%3}, {%4,%5,%6,%7}, {%8,%9}, {%0,%1,%2,%3};"
        : "+f"(c[0]), "+f"(c[1]), "+f"(c[2]), "+f"(c[3])
        : "r"(a[0]), "r"(a[1]), "r"(a[2]), "r"(a[3]), "r"(b[0]), "r"(b[1]));
}
__device__ __forceinline__ void ldsm_x4(uint32_t* r, uint32_t saddr) {
    asm volatile("ldmatrix.sync.aligned.m8n8.x4.shared.b16 {%0,%1,%2,%3}, [%4];"
                 : "=r"(r[0]), "=r"(r[1]), "=r"(r[2]), "=r"(r[3]) : "r"(saddr));
}
__device__ __forceinline__ void ldsm_x4_t(uint32_t* r, uint32_t saddr) {
    asm volatile("ldmatrix.sync.aligned.m8n8.x4.trans.shared.b16 {%0,%1,%2,%3}, [%4];"
                 : "=r"(r[0]), "=r"(r[1]), "=r"(r[2]), "=r"(r[3]) : "r"(saddr));
}

// JAX default gelu: approximate=True (tanh form)
__device__ __forceinline__ float gelu_tanh(float v) {
    float t = tanhf(0.7978845608028654f * (v + 0.044715f * v * v * v));
    return 0.5f * v * (1.0f + t);
}

// ---------------- stage 0: zero out + counts (out receives atomic combine) ----------------
__global__ void zero_out_kernel(float4* __restrict__ out) {
    const int i = blockIdx.x * blockDim.x + threadIdx.x;
    out[i] = make_float4(0.f, 0.f, 0.f, 0.f);
    if (blockIdx.x == 0 && threadIdx.x < NEXP) g_counts[threadIdx.x] = 0;
}

// ---------------- stage 0b: fp32 -> fp16 convert (weights) ----------------
__global__ void to_half_kernel(const float4* __restrict__ in, __half2* __restrict__ outp, int n4) {
    int i = blockIdx.x * blockDim.x + threadIdx.x;
    if (i < n4) {
        float4 v = in[i];
        outp[2 * i + 0] = __floats2half2_rn(v.x, v.y);
        outp[2 * i + 1] = __floats2half2_rn(v.z, v.w);
    }
}

// ---------------- stage 1: gating (top-2 softmax + expert lists) + x->fp16 ----------------
__global__ void gate_kernel(const float* __restrict__ x, const float* __restrict__ wg) {
    const int n = blockIdx.x;
    const int tid = threadIdx.x;                 // 128 threads
    const float* xr = x + (size_t)n * DDIM;

    float acc[NEXP];
#pragma unroll
    for (int e = 0; e < NEXP; e++) acc[e] = 0.0f;
    for (int d = tid; d < DDIM; d += 128) {
        float xv = xr[d];
        g_xh[(size_t)n * DDIM + d] = __float2half_rn(xv);   // fused x conversion
        const float* w = wg + d * NEXP;
#pragma unroll
        for (int e = 0; e < NEXP; e++) acc[e] += xv * w[e];
    }
#pragma unroll
    for (int e = 0; e < NEXP; e++) {
#pragma unroll
        for (int o = 16; o > 0; o >>= 1) acc[e] += __shfl_xor_sync(0xffffffffu, acc[e], o);
    }
    __shared__ float sred[4][NEXP];
    const int wid = tid >> 5, lane = tid & 31;
    if (lane == 0) {
#pragma unroll
        for (int e = 0; e < NEXP; e++) sred[wid][e] = acc[e];
    }
    __syncthreads();
    if (tid == 0) {
        float lg[NEXP];
#pragma unroll
        for (int e = 0; e < NEXP; e++)
            lg[e] = sred[0][e] + sred[1][e] + sred[2][e] + sred[3][e];
        int i0 = 0;
#pragma unroll
        for (int e = 1; e < NEXP; e++) if (lg[e] > lg[i0]) i0 = e;
        int i1 = (i0 == 0) ? 1 : 0;
#pragma unroll
        for (int e = 0; e < NEXP; e++) if (e != i0 && lg[e] > lg[i1]) i1 = e;
        float e1 = __expf(lg[i1] - lg[i0]);
        float inv = 1.0f / (1.0f + e1);

        int s0 = atomicAdd(&g_counts[i0], 1);
        int s1 = atomicAdd(&g_counts[i1], 1);
        g_tok[i0 * NTOK + s0] = n;   g_gslot[i0 * NTOK + s0] = inv;
        g_tok[i1 * NTOK + s1] = n;   g_gslot[i1 * NTOK + s1] = e1 * inv;
    }
}

// ---------------- stages 2/3: grouped GEMM, fp16 mma.sync m16n8k16 ----------------
// Tile 128 x 128, BK=32, 4-stage cp.async, 256 thr, 2 CTAs/SM (proven R15 core).
// PHASE 1: h = gelu(x@w1+b1) -> g_hh (fp16).
// PHASE 2: epilogue fuses the top-2 combine: out[token] += gate * (acc + b2)
//   via atomicAdd. Deterministic: each token gets EXACTLY 2 contributions into
//   a zeroed buffer, and a two-term float sum is order-invariant.

#define A_STRIDE 40          // halfs per A smem row (32 k + 8 pad; rows bank-disjoint)
#define B_STRIDE 136         // halfs per B smem row (128 n + 8 pad; k-rows bank-disjoint)
#define A_STAGE  (128 * A_STRIDE)            // 5120 halfs
#define B_STAGE  (32 * B_STRIDE)             // 4352 halfs
#define SMEM_HALFS (4 * (A_STAGE + B_STAGE))
#define SMEM_BYTES (SMEM_HALFS * 2)          // 75,776 B -> 2 CTAs/SM

template <int PHASE>
__global__ void __launch_bounds__(256, 2) ffn_gemm_kernel(
    const __half* __restrict__ x, const __half* __restrict__ w_all,
    const float* __restrict__ bias_all, float* __restrict__ out) {
    constexpr int KD   = (PHASE == 1) ? DDIM : HDIM;
    constexpr int NOUT = (PHASE == 1) ? HDIM : DDIM;
    constexpr int KT   = KD / 32;

    const int e  = blockIdx.z;
    const int tm = blockIdx.y;
    const int tn = blockIdx.x;
    const int cnt = g_counts[e];
    if (tm * 128 >= cnt) return;
    const int rows = min(128, cnt - tm * 128);

    extern __shared__ __half smem[];
    __half* const Abase = smem;                      // 4 stages x A_STAGE
    __half* const Bbase = smem + 4 * A_STAGE;        // 4 stages x B_STAGE
    const uint32_t sbase = (uint32_t)__cvta_generic_to_shared(smem);

    const int tid  = threadIdx.x;
    const int lane = tid & 31, wid = tid >> 5;
    const int wm = wid >> 2, wn = wid & 3;           // 2 x 4 warp grid, 64x32 per warp
    const int grp = lane >> 2, tig = lane & 3;

    // ---- per-thread cp.async assignments ----
    const __half* ag[2];
    int aoff[2];
    const __half* wsrc = w_all + (size_t)e * ((size_t)KD * NOUT);
#pragma unroll
    for (int j = 0; j < 2; j++) {
        const int linear = j * 256 + tid;
        const int ar = linear >> 2;                  // row 0..127
        const int ac = (linear & 3) * 8;             // half offset 0/8/16/24
        if (PHASE == 1) {
            const int tk = g_tok[e * NTOK + tm * 128 + ar];
            ag[j] = x + (size_t)tk * DDIM + ac;
        } else {
            ag[j] = g_hh + ((size_t)e * NTOK + tm * 128 + ar) * HDIM + ac;
        }
        aoff[j] = ar * A_STRIDE + ac;
    }
    const __half* bg[2];
    int boff[2];
#pragma unroll
    for (int j = 0; j < 2; j++) {
        const int linear = j * 256 + tid;
        const int br = linear >> 4;                  // k-row 0..31
        const int bc = (linear & 15) * 8;            // n-half offset 0..120
        bg[j]   = wsrc + (size_t)br * NOUT + (size_t)tn * 128 + bc;
        boff[j] = br * B_STRIDE + bc;
    }

    auto issue = [&](int it, int stage) {
        __half* As = Abase + stage * A_STAGE;
        __half* Bs = Bbase + stage * B_STAGE;
#pragma unroll
        for (int j = 0; j < 2; j++) cpasync16(As + aoff[j], ag[j] + it * 32);
#pragma unroll
        for (int j = 0; j < 2; j++) cpasync16(Bs + boff[j], bg[j] + (size_t)it * 32 * NOUT);
    };

    // ---- ldmatrix lane address components ----
    const int l15 = lane & 15, lhi = lane >> 4;
    const int aLane = (wm * 64 + l15) * A_STRIDE + lhi * 8;
    const int bLane = l15 * B_STRIDE + wn * 32 + lhi * 8;

    float acc[4][4][4];
#pragma unroll
    for (int mi = 0; mi < 4; mi++)
#pragma unroll
        for (int ni = 0; ni < 4; ni++)
#pragma unroll
            for (int q = 0; q < 4; q++) acc[mi][ni][q] = 0.0f;

    // ---- prologue: 3 stages in flight ----
    issue(0, 0); cp_commit();
    issue(1, 1); cp_commit();
    issue(2, 2); cp_commit();

    for (int it = 0; it < KT; it++) {
        const int stage = it & 3;
        cp_wait2();                                  // stage `it` landed
        __syncthreads();                             // everyone done reading stage (it-1)&3
        if (it + 3 < KT) issue(it + 3, (it + 3) & 3);
        cp_commit();                                 // empty commit at tail keeps count math

        const uint32_t aSt = sbase + (uint32_t)((stage * A_STAGE + aLane) * 2);
        const uint32_t bSt = sbase + (uint32_t)((4 * A_STAGE + stage * B_STAGE + bLane) * 2);
#pragma unroll
        for (int ks = 0; ks < 2; ks++) {             // two k16 steps per BK=32
            uint32_t af[4][4], bf[4][2];
#pragma unroll
            for (int mi = 0; mi < 4; mi++)
                ldsm_x4(af[mi], aSt + (uint32_t)((mi * 16 * A_STRIDE + ks * 16) * 2));
#pragma unroll
            for (int p = 0; p < 2; p++) {
                uint32_t t[4];
                ldsm_x4_t(t, bSt + (uint32_t)((ks * 16 * B_STRIDE + p * 16) * 2));
                bf[2 * p][0] = t[0]; bf[2 * p][1] = t[1];
                bf[2 * p + 1][0] = t[2]; bf[2 * p + 1][1] = t[3];
            }
#pragma unroll
            for (int mi = 0; mi < 4; mi++)
#pragma unroll
                for (int ni = 0; ni < 4; ni++)
                    mma_f16(acc[mi][ni], af[mi], bf[ni]);
        }
        // no trailing sync: next iteration's leading sync protects stage reuse
    }

    // ---- epilogue ----
    const float* bias = bias_all + e * NOUT;
    const size_t rowbase = (size_t)e * NTOK + (size_t)tm * 128;
#pragma unroll
    for (int mi = 0; mi < 4; mi++) {
        const int lr0 = wm * 64 + mi * 16 + grp;
        const int lr1 = lr0 + 8;
        // per-row token + gate (PHASE 2 combine); cached loads, hoisted over ni
        int   tk0 = 0, tk1 = 0;
        float gv0 = 0.f, gv1 = 0.f;
        if (PHASE == 2) {
            if (lr0 < rows) {
                tk0 = g_tok[rowbase + lr0];
                gv0 = g_gslot[rowbase + lr0];
            }
            if (lr1 < rows) {
                tk1 = g_tok[rowbase + lr1];
                gv1 = g_gslot[rowbase + lr1];
            }
        }
#pragma unroll
        for (int ni = 0; ni < 4; ni++) {
            const int col = tn * 128 + wn * 32 + ni * 8 + tig * 2;
            const float bv0 = bias[col], bv1 = bias[col + 1];
            float v00 = acc[mi][ni][0] + bv0, v01 = acc[mi][ni][1] + bv1;
            float v10 = acc[mi][ni][2] + bv0, v11 = acc[mi][ni][3] + bv1;
            if (PHASE == 1) {
                __half2 h0 = __floats2half2_rn(gelu_tanh(v00), gelu_tanh(v01));
                __half2 h1 = __floats2half2_rn(gelu_tanh(v10), gelu_tanh(v11));
                if (lr0 < rows)
                    *(__half2*)(g_hh + (rowbase + lr0) * HDIM + col) = h0;
                if (lr1 < rows)
                    *(__half2*)(g_hh + (rowbase + lr1) * HDIM + col) = h1;
            } else {
                if (lr0 < rows) {
                    float* o = out + (size_t)tk0 * DDIM + col;
                    atomicAdd(o,     gv0 * v00);
                    atomicAdd(o + 1, gv0 * v01);
                }
                if (lr1 < rows) {
                    float* o = out + (size_t)tk1 * DDIM + col;
                    atomicAdd(o,     gv1 * v10);
                    atomicAdd(o + 1, gv1 * v11);
                }
            }
        }
    }
}

// ---------------- launch ----------------
extern "C" void kernel_launch(void* const* d_in, const int* in_sizes, int n_in,
                              void* d_out, int out_size) {
    const float* x  = (const float*)d_in[0];   // [N, D]
    const float* wg = (const float*)d_in[1];   // [D, E]
    const float* w1 = (const float*)d_in[2];   // [E, D, H]
    const float* b1 = (const float*)d_in[3];   // [E, H]
    const float* w2 = (const float*)d_in[4];   // [E, H, D]
    const float* b2 = (const float*)d_in[5];   // [E, D]
    float* out = (float*)d_out;

    __half* xh;  cudaGetSymbolAddress((void**)&xh,  g_xh);
    __half* w1h; cudaGetSymbolAddress((void**)&w1h, g_w1h);
    __half* w2h; cudaGetSymbolAddress((void**)&w2h, g_w2h);

    cudaFuncSetAttribute(ffn_gemm_kernel<1>, cudaFuncAttributeMaxDynamicSharedMemorySize, SMEM_BYTES);
    cudaFuncSetAttribute(ffn_gemm_kernel<2>, cudaFuncAttributeMaxDynamicSharedMemorySize, SMEM_BYTES);

    // zero out (atomic-combine target) + counts in one launch
    zero_out_kernel<<<NTOK * DDIM / 4 / 256, 256>>>((float4*)out);

    gate_kernel<<<NTOK, 128>>>(x, wg);     // also produces fp16 x

    {   // weight fp32 -> fp16
        int m4 = NEXP * DDIM * HDIM / 4;
        to_half_kernel<<<(m4 + 255) / 256, 256>>>((const float4*)w1, (__half2*)w1h, m4);
        to_half_kernel<<<(m4 + 255) / 256, 256>>>((const float4*)w2, (__half2*)w2h, m4);
    }

    ffn_gemm_kernel<1><<<dim3(HDIM / 128, NTOK / 128, NEXP), 256, SMEM_BYTES>>>(xh, w1h, b1, out);
    ffn_gemm_kernel<2><<<dim3(DDIM / 128, NTOK / 128, NEXP), 256, SMEM_BYTES>>>(xh, w2h, b2, out);
}